// round 6
// baseline (speedup 1.0000x reference)
#include <cuda_runtime.h>

// Problem shape (fixed by the reference): (16, 1, 1024, 1024) fp32.
#define NB    16
#define HW    (1024 * 1024)
#define TOTAL (NB * HW)
#define N4    (TOTAL / 4)
#define HW4   (HW / 4)         // 262144 float4 per batch
#define HW4_SHIFT 18           // log2(HW4)

// Scratch (allocation-free rule: __device__ globals).
__device__ unsigned int g_hist[NB][256];   // jnp.histogram bins
__device__ unsigned int g_vhist[NB][256];  // count of valid pixels per rounded index
__device__ float        g_scale[NB];       // 0.0 if mask.max()==0 else 1.0

// ---------------------------------------------------------------------------
// K0: zero the counters (must run every replay — graph determinism)
// ---------------------------------------------------------------------------
__global__ void wsm_zero_kernel() {
    int b = blockIdx.x, t = threadIdx.x;
    g_hist[b][t]  = 0u;
    g_vhist[b][t] = 0u;
    if (t == 0) g_scale[b] = 0.0f;
}

// ---------------------------------------------------------------------------
// K1: per-batch histograms.
//   mi = irr * 255   (bit-exact match to the reference: input * 255.0f)
//   hist bin (jnp.histogram, 256 bins over [0,255]): floor(mi * 256/255),
//     v == 255 goes to bin 255 (last bin inclusive). True edges are never
//     within ~4e-3 of an integer value for i in 1..254, so fp32 rounding of
//     the scale cannot flip a bin.
//   valid: mi == rint(mi) && 0 <= mi <= 255  (rintf = round-half-even = jnp.round)
// ---------------------------------------------------------------------------
__global__ void __launch_bounds__(256) wsm_hist_kernel(const float* __restrict__ irr) {
    __shared__ unsigned int sh[256];
    __shared__ unsigned int sv[256];
    const int t = threadIdx.x;
    sh[t] = 0u;
    sv[t] = 0u;
    __syncthreads();

    const int b = blockIdx.y;
    const float4* __restrict__ in4 =
        reinterpret_cast<const float4*>(irr + (size_t)b * HW);
    const int stride = blockDim.x * gridDim.x;

    for (int i = blockIdx.x * blockDim.x + t; i < HW4; i += stride) {
        float4 v4 = in4[i];
        float vals[4] = {v4.x, v4.y, v4.z, v4.w};
#pragma unroll
        for (int k = 0; k < 4; k++) {
            float v = vals[k] * 255.0f;
            if (v >= 0.0f && v <= 255.0f) {
                int bin = (int)(v * (256.0f / 255.0f));
                if (bin > 255) bin = 255;
                atomicAdd(&sh[bin], 1u);
                float r = rintf(v);
                if (v == r) atomicAdd(&sv[(int)r], 1u);
            }
            // v outside [0,255]: not in hist range, and "valid" requires
            // r in [0,255] with v==r, which the range check already excludes.
        }
    }
    __syncthreads();
    atomicAdd(&g_hist[b][t],  sh[t]);
    atomicAdd(&g_vhist[b][t], sv[t]);
}

// ---------------------------------------------------------------------------
// K2: per-batch flag.
//   mask_output[r] = sum_j |r - j| * hist[j]   (all terms >= 0)
//   mask.max() > 0  <=>  exists r with vhist[r] > 0 and mask_output[r] > 0
// ---------------------------------------------------------------------------
__global__ void __launch_bounds__(256) wsm_flag_kernel() {
    const int b = blockIdx.x;
    const int r = threadIdx.x;
    __shared__ float sh[256];
    sh[r] = (float)g_hist[b][r];
    __syncthreads();

    float mo = 0.0f;
#pragma unroll 8
    for (int j = 0; j < 256; j++) {
        mo += fabsf((float)(r - j)) * sh[j];
    }
    int nz  = (g_vhist[b][r] > 0u) && (mo > 0.0f);
    int any = __syncthreads_or(nz);
    if (r == 0) g_scale[b] = any ? 1.0f : 0.0f;
}

// ---------------------------------------------------------------------------
// K3: elementwise output (the only real bandwidth cost).
//   m  = scale * ((irr*255)/255)
//   out0 = softmax num 0 = 1/(1+e^(1-2m))
//   out1 = e^(1-2m)/(1+e^(1-2m))
// ---------------------------------------------------------------------------
__global__ void __launch_bounds__(256) wsm_out_kernel(const float* __restrict__ irr,
                                                      float* __restrict__ out) {
    int i = blockIdx.x * blockDim.x + threadIdx.x;
    if (i >= N4) return;
    const float4* __restrict__ in4 = reinterpret_cast<const float4*>(irr);
    float4* __restrict__ o0 = reinterpret_cast<float4*>(out);
    float4* __restrict__ o1 = reinterpret_cast<float4*>(out + (size_t)TOTAL);

    const int b = i >> HW4_SHIFT;           // batch index (HW divisible by 4)
    const float s = g_scale[b];

    float4 v = in4[i];
    float4 p0, p1;
    {
        float m = s * ((v.x * 255.0f) / 255.0f);
        float e = expf(1.0f - 2.0f * m);
        float d = 1.0f / (1.0f + e);
        p0.x = d; p1.x = e * d;
    }
    {
        float m = s * ((v.y * 255.0f) / 255.0f);
        float e = expf(1.0f - 2.0f * m);
        float d = 1.0f / (1.0f + e);
        p0.y = d; p1.y = e * d;
    }
    {
        float m = s * ((v.z * 255.0f) / 255.0f);
        float e = expf(1.0f - 2.0f * m);
        float d = 1.0f / (1.0f + e);
        p0.z = d; p1.z = e * d;
    }
    {
        float m = s * ((v.w * 255.0f) / 255.0f);
        float e = expf(1.0f - 2.0f * m);
        float d = 1.0f / (1.0f + e);
        p0.w = d; p1.w = e * d;
    }
    o0[i] = p0;
    o1[i] = p1;
}

// ---------------------------------------------------------------------------
// Launch. d_in[0] = image_irr (16M fp32), d_in[1] = image_vis (unused).
// d_out = 2 * 16M fp32 (msks[0] then msks[1], concatenated).
// ---------------------------------------------------------------------------
extern "C" void kernel_launch(void* const* d_in, const int* in_sizes, int n_in,
                              void* d_out, int out_size) {
    const float* irr = (const float*)d_in[0];
    float* out = (float*)d_out;

    wsm_zero_kernel<<<NB, 256>>>();

    dim3 hgrid(128, NB, 1);
    wsm_hist_kernel<<<hgrid, 256>>>(irr);

    wsm_flag_kernel<<<NB, 256>>>();

    int blocks = (N4 + 255) / 256;
    wsm_out_kernel<<<blocks, 256>>>(irr, out);
}

// round 9
// speedup vs baseline: 1.1507x; 1.1507x over previous
#include <cuda_runtime.h>

// Problem shape (fixed by the reference): (16, 1, 1024, 1024) fp32.
#define NB     16
#define HW     (1024 * 1024)
#define TOTAL  (NB * HW)
#define N4     (TOTAL / 4)
#define HW4    (HW / 4)          // 262144 float4 per batch
#define SBLK   128               // stats blocks per batch

// Scratch (allocation-free rule: __device__ globals).
// g_part[b][x] = {min_bin, max_bin, min_valid_idx, max_valid_idx} for that
// block's slice. Plain overwrite every replay -> deterministic, no zeroing.
__device__ int4  g_part[NB][SBLK];
__device__ float g_nscale[NB];   // -2 * scale  (scale in {0,1})

// ---------------------------------------------------------------------------
// K1: per-batch streaming stats (replaces the histogram).
//
// Why this suffices: mask_output[r] = sum_j |r-j| * hist[j].
//   - hist empty (no in-range pixel)        -> mask_output == 0 -> flag 0
//   - >= 2 distinct occupied bins           -> mask_output[r] > 0 for all r
//                                              -> flag = (any valid pixel)
//   - exactly 1 occupied bin b0             -> mask_output[r] = N*|r-b0|,
//                                              zero only at r=b0
//                                              -> flag = exists valid idx != b0
// So we only need min/max occupied bin and min/max valid index.
//   mi  = irr * 255 (fp32, identical to the reference computation)
//   bin = floor(mi * 256/255), last edge inclusive (jnp.histogram, range (0,255));
//         true interior edges are >= 1/255 away from the near-integer data, so
//         fp32 rounding cannot flip a bin.
//   valid: mi == rintf(mi) (round-half-even == jnp.round) && 0 <= mi <= 255
// ---------------------------------------------------------------------------
__global__ void __launch_bounds__(256) wsm_stats_kernel(const float* __restrict__ irr) {
    const int b = blockIdx.y;
    const float4* __restrict__ in4 =
        reinterpret_cast<const float4*>(irr + (size_t)b * HW);

    int mnb = 256, mxb = -1;   // occupied-bin min/max (256/-1 = none)
    int mni = 256, mxi = -1;   // valid-index min/max  (256/-1 = none)

    const int stride = 256 * SBLK;
    for (int i = blockIdx.x * 256 + threadIdx.x; i < HW4; i += stride) {
        float4 v4 = in4[i];
        float vs[4] = {v4.x, v4.y, v4.z, v4.w};
#pragma unroll
        for (int k = 0; k < 4; k++) {
            float v = vs[k] * 255.0f;
            if (v >= 0.0f && v <= 255.0f) {
                int bin = (int)(v * (256.0f / 255.0f));
                if (bin > 255) bin = 255;
                mnb = min(mnb, bin);
                mxb = max(mxb, bin);
                float r = rintf(v);
                if (v == r) {
                    int idx = (int)r;
                    mni = min(mni, idx);
                    mxi = max(mxi, idx);
                }
            }
            // v outside [0,255]: excluded from hist; "valid" needs v==r with
            // r in [0,255], contradicting the range check -> nothing to track.
        }
    }

    // warp redux, then cross-warp via shared
    mnb = __reduce_min_sync(0xffffffffu, mnb);
    mxb = __reduce_max_sync(0xffffffffu, mxb);
    mni = __reduce_min_sync(0xffffffffu, mni);
    mxi = __reduce_max_sync(0xffffffffu, mxi);

    __shared__ int s_mnb[8], s_mxb[8], s_mni[8], s_mxi[8];
    const int w = threadIdx.x >> 5, l = threadIdx.x & 31;
    if (l == 0) { s_mnb[w] = mnb; s_mxb[w] = mxb; s_mni[w] = mni; s_mxi[w] = mxi; }
    __syncthreads();
    if (threadIdx.x < 32) {
        const int j = threadIdx.x & 7;   // replicate across lanes; min/max idempotent
        mnb = __reduce_min_sync(0xffffffffu, s_mnb[j]);
        mxb = __reduce_max_sync(0xffffffffu, s_mxb[j]);
        mni = __reduce_min_sync(0xffffffffu, s_mni[j]);
        mxi = __reduce_max_sync(0xffffffffu, s_mxi[j]);
        if (threadIdx.x == 0)
            g_part[b][blockIdx.x] = make_int4(mnb, mxb, mni, mxi);
    }
}

// ---------------------------------------------------------------------------
// K2: reduce the 128 partials per batch, derive the flag, store ns = -2*scale.
// ---------------------------------------------------------------------------
__global__ void __launch_bounds__(SBLK) wsm_flag_kernel() {
    const int b = blockIdx.x;
    int4 p = g_part[b][threadIdx.x];
    int mnb = p.x, mxb = p.y, mni = p.z, mxi = p.w;

    mnb = __reduce_min_sync(0xffffffffu, mnb);
    mxb = __reduce_max_sync(0xffffffffu, mxb);
    mni = __reduce_min_sync(0xffffffffu, mni);
    mxi = __reduce_max_sync(0xffffffffu, mxi);

    __shared__ int s_mnb[4], s_mxb[4], s_mni[4], s_mxi[4];
    const int w = threadIdx.x >> 5, l = threadIdx.x & 31;
    if (l == 0) { s_mnb[w] = mnb; s_mxb[w] = mxb; s_mni[w] = mni; s_mxi[w] = mxi; }
    __syncthreads();
    if (threadIdx.x == 0) {
        mnb = min(min(s_mnb[0], s_mnb[1]), min(s_mnb[2], s_mnb[3]));
        mxb = max(max(s_mxb[0], s_mxb[1]), max(s_mxb[2], s_mxb[3]));
        mni = min(min(s_mni[0], s_mni[1]), min(s_mni[2], s_mni[3]));
        mxi = max(max(s_mxi[0], s_mxi[1]), max(s_mxi[2], s_mxi[3]));

        const bool any_range = (mnb <= mxb);
        const bool any_valid = (mni <= mxi);
        int flag;
        if (!any_range)        flag = 0;                         // hist empty
        else if (mnb != mxb)   flag = any_valid ? 1 : 0;         // mask_output > 0 everywhere
        else                   flag = (any_valid && (mni != mnb || mxi != mnb)) ? 1 : 0;
        g_nscale[b] = flag ? -2.0f : 0.0f;                       // ns = -2*scale
    }
}

// ---------------------------------------------------------------------------
// K3: elementwise output (the real bandwidth cost).
//   m    = scale * v          ( == scale*(v*255)/255 within 1 ulp; tol 1e-3 )
//   out0 = 1/(1 + e^(1-2m))   = sigmoid(2m-1)
//   out1 = 1 - out0
// Per element: FFMA + (FMUL+MUFU.EX2) + FADD + MUFU.RCP + FADD.
// ---------------------------------------------------------------------------
__global__ void __launch_bounds__(256) wsm_out_kernel(const float* __restrict__ irr,
                                                      float* __restrict__ out) {
    const int i = blockIdx.x * 256 + threadIdx.x;        // N4 = 16384*256 exactly
    const float ns = g_nscale[blockIdx.x >> 10];         // 1024 blocks per batch

    const float4* __restrict__ in4 = reinterpret_cast<const float4*>(irr);
    float4* __restrict__ o0 = reinterpret_cast<float4*>(out);
    float4* __restrict__ o1 = reinterpret_cast<float4*>(out + (size_t)TOTAL);

    float4 v = in4[i];
    float4 p0, p1;
    {
        float e = __expf(fmaf(ns, v.x, 1.0f));
        float d = __fdividef(1.0f, 1.0f + e);
        p0.x = d; p1.x = 1.0f - d;
    }
    {
        float e = __expf(fmaf(ns, v.y, 1.0f));
        float d = __fdividef(1.0f, 1.0f + e);
        p0.y = d; p1.y = 1.0f - d;
    }
    {
        float e = __expf(fmaf(ns, v.z, 1.0f));
        float d = __fdividef(1.0f, 1.0f + e);
        p0.z = d; p1.z = 1.0f - d;
    }
    {
        float e = __expf(fmaf(ns, v.w, 1.0f));
        float d = __fdividef(1.0f, 1.0f + e);
        p0.w = d; p1.w = 1.0f - d;
    }
    o0[i] = p0;
    o1[i] = p1;
}

// ---------------------------------------------------------------------------
// Launch. d_in[0] = image_irr (16M fp32), d_in[1] = image_vis (dead in the
// reference — never read). d_out = msks[0] then msks[1], concatenated.
// ---------------------------------------------------------------------------
extern "C" void kernel_launch(void* const* d_in, const int* in_sizes, int n_in,
                              void* d_out, int out_size) {
    const float* irr = (const float*)d_in[0];
    float* out = (float*)d_out;

    dim3 sgrid(SBLK, NB, 1);
    wsm_stats_kernel<<<sgrid, 256>>>(irr);

    wsm_flag_kernel<<<NB, SBLK>>>();

    wsm_out_kernel<<<N4 / 256, 256>>>(irr, out);
}

// round 11
// speedup vs baseline: 1.4717x; 1.2789x over previous
#include <cuda_runtime.h>

// Problem shape (fixed by the reference): (16, 1, 1024, 1024) fp32.
#define NB     16
#define HW     (1024 * 1024)
#define TOTAL  (NB * HW)
#define N4     (TOTAL / 4)
#define HW4    (HW / 4)          // 262144 float4 per batch
#define SBLK   64                // stats blocks per batch

// Scratch (allocation-free rule: __device__ globals). Plain overwrite every
// replay -> deterministic, graph-safe, no zeroing kernel needed.
// g_part[b][x]: {min_bin, max_bin, min_valid_idx, max_valid_idx} for a full
// scan, or {-2,-2,-2,-2} = "flag determined to be 1 by this block".
__device__ int4  g_part[NB][SBLK];
__device__ float g_nscale[NB];   // -2 * scale  (scale in {0,1})

// ---------------------------------------------------------------------------
// helpers
// ---------------------------------------------------------------------------
__device__ __forceinline__ float warp_minf(float v) {
#pragma unroll
    for (int o = 16; o; o >>= 1) v = fminf(v, __shfl_xor_sync(0xffffffffu, v, o));
    return v;
}
__device__ __forceinline__ float warp_maxf(float v) {
#pragma unroll
    for (int o = 16; o; o >>= 1) v = fmaxf(v, __shfl_xor_sync(0xffffffffu, v, o));
    return v;
}

// Block-wide reduce of (min, max, min, max). 256 threads = 8 warps.
__device__ __forceinline__ void block_reduce4(float& mnv, float& mxv,
                                              float& mnvv, float& mxvv) {
    __shared__ float sm[4][8];
    __syncthreads();                       // protect sm across repeated calls
    float a = warp_minf(mnv), b = warp_maxf(mxv);
    float c = warp_minf(mnvv), d = warp_maxf(mxvv);
    const int w = threadIdx.x >> 5, l = threadIdx.x & 31;
    if (l == 0) { sm[0][w] = a; sm[1][w] = b; sm[2][w] = c; sm[3][w] = d; }
    __syncthreads();
    a = sm[0][0]; b = sm[1][0]; c = sm[2][0]; d = sm[3][0];
#pragma unroll
    for (int j = 1; j < 8; j++) {
        a = fminf(a, sm[0][j]); b = fmaxf(b, sm[1][j]);
        c = fminf(c, sm[2][j]); d = fmaxf(d, sm[3][j]);
    }
    mnv = a; mxv = b; mnvv = c; mxvv = d;
}

// jnp.histogram bin over range (0,255), 256 bins, last edge inclusive.
// Monotone non-decreasing in v, so bin(min v) / bin(max v) give min/max bin.
__device__ __forceinline__ int bin_of(float v) {
    int b = (int)(v * (256.0f / 255.0f));
    return b > 255 ? 255 : b;
}

__device__ __forceinline__ void acc_elem(float x, float& mnv, float& mxv,
                                         float& mnvv, float& mxvv) {
    float v = x * 255.0f;                          // identical to reference mi
    bool inr = (v >= 0.0f) && (v <= 255.0f);
    float r = rintf(v);                            // round-half-even == jnp.round
    bool val = inr && (v == r);                    // valid mask pixel
    if (inr) { mnv  = fminf(mnv,  v); mxv  = fmaxf(mxv,  v); }
    if (val) { mnvv = fminf(mnvv, v); mxvv = fmaxf(mxvv, v); }
}

// ---------------------------------------------------------------------------
// K1: per-batch stats with EARLY EXIT.
//
// flag = 1 iff mask.max() > 0, where mask_output[r] = sum_j |r-j|*hist[j]:
//   - hist empty                      -> flag 0
//   - >= 2 distinct occupied bins     -> mask_output[r] > 0 for ALL r
//                                        -> flag = (any valid pixel)
//   - exactly 1 occupied bin b0       -> zero only at r = b0
//                                        -> flag = exists valid idx != b0
//
// "≥2 distinct occupied bins" and "≥1 valid pixel" are monotone in the data:
// local evidence in ANY block implies them globally. So after the first tile
// each block reduces; if both hold locally it writes a sentinel and exits
// without reading the rest of its slice (correct for all inputs — blocks that
// cannot determine fall through to the full scan, whose min/max partials let
// K2 resolve the degenerate cases exactly).
// ---------------------------------------------------------------------------
__global__ void __launch_bounds__(256) wsm_stats_kernel(const float* __restrict__ irr) {
    const int b = blockIdx.y;
    const float4* __restrict__ in4 =
        reinterpret_cast<const float4*>(irr + (size_t)b * HW);

    float mnv = 1e30f, mxv = -1e30f;     // in-range v    (empty: mnv > mxv)
    float mnvv = 1e30f, mxvv = -1e30f;   // valid v       (empty: mnvv > mxvv)

    const int stride = 256 * SBLK;
    int i = blockIdx.x * 256 + threadIdx.x;

    // ---- phase 1: one float4 per thread ----
    {
        float4 v4 = in4[i];
        acc_elem(v4.x, mnv, mxv, mnvv, mxvv);
        acc_elem(v4.y, mnv, mxv, mnvv, mxvv);
        acc_elem(v4.z, mnv, mxv, mnvv, mxvv);
        acc_elem(v4.w, mnv, mxv, mnvv, mxvv);
    }
    float a = mnv, bx = mxv, c = mnvv, d = mxvv;
    block_reduce4(a, bx, c, d);
    const bool det = (a <= bx) && (c <= d) && (bin_of(a) != bin_of(bx));
    if (det) {
        if (threadIdx.x == 0)
            g_part[b][blockIdx.x] = make_int4(-2, -2, -2, -2);
        return;
    }

    // ---- fallback: full scan of the remaining slice ----
    for (i += stride; i < HW4; i += stride) {
        float4 v4 = in4[i];
        acc_elem(v4.x, mnv, mxv, mnvv, mxvv);
        acc_elem(v4.y, mnv, mxv, mnvv, mxvv);
        acc_elem(v4.z, mnv, mxv, mnvv, mxvv);
        acc_elem(v4.w, mnv, mxv, mnvv, mxvv);
    }
    block_reduce4(mnv, mxv, mnvv, mxvv);
    if (threadIdx.x == 0) {
        int mnb, mxb, mni, mxi;
        if (mnv <= mxv) { mnb = bin_of(mnv); mxb = bin_of(mxv); }
        else            { mnb = 256; mxb = -1; }
        if (mnvv <= mxvv) { mni = (int)mnvv; mxi = (int)mxvv; }  // already exact ints
        else              { mni = 256; mxi = -1; }
        g_part[b][blockIdx.x] = make_int4(mnb, mxb, mni, mxi);
    }
}

// ---------------------------------------------------------------------------
// K2: combine partials per batch, store ns = -2*scale.
// ---------------------------------------------------------------------------
__global__ void __launch_bounds__(32) wsm_flag_kernel() {
    const int b = blockIdx.x;
    int mnb = 256, mxb = -1, mni = 256, mxi = -1, det = 0;
    for (int j = threadIdx.x; j < SBLK; j += 32) {
        int4 p = g_part[b][j];
        if (p.x == -2) det = 1;
        else {
            mnb = min(mnb, p.x); mxb = max(mxb, p.y);
            mni = min(mni, p.z); mxi = max(mxi, p.w);
        }
    }
    det = __any_sync(0xffffffffu, det);
    mnb = __reduce_min_sync(0xffffffffu, mnb);
    mxb = __reduce_max_sync(0xffffffffu, mxb);
    mni = __reduce_min_sync(0xffffffffu, mni);
    mxi = __reduce_max_sync(0xffffffffu, mxi);
    if (threadIdx.x == 0) {
        int flag;
        if (det) flag = 1;
        else {
            const bool any_range = (mnb <= mxb);
            const bool any_valid = (mni <= mxi);
            if (!any_range)      flag = 0;                        // hist empty
            else if (mnb != mxb) flag = any_valid ? 1 : 0;        // >=2 bins
            else                 flag = (any_valid && (mni != mnb || mxi != mnb)) ? 1 : 0;
        }
        g_nscale[b] = flag ? -2.0f : 0.0f;                        // ns = -2*scale
    }
}

// ---------------------------------------------------------------------------
// K3: elementwise output (the real bandwidth cost, ~192 MB).
//   m    = scale * v
//   out0 = 1/(1 + e^(1-2m)),  out1 = 1 - out0
// Streaming loads/stores (.cs): nothing here is ever reused.
// ---------------------------------------------------------------------------
__global__ void __launch_bounds__(256) wsm_out_kernel(const float* __restrict__ irr,
                                                      float* __restrict__ out) {
    const int i = blockIdx.x * 256 + threadIdx.x;        // N4 = 16384*256 exactly
    const float ns = g_nscale[blockIdx.x >> 10];         // 1024 blocks per batch

    const float4* __restrict__ in4 = reinterpret_cast<const float4*>(irr);
    float4* __restrict__ o0 = reinterpret_cast<float4*>(out);
    float4* __restrict__ o1 = reinterpret_cast<float4*>(out + (size_t)TOTAL);

    float4 v = __ldcs(&in4[i]);
    float4 p0, p1;
    {
        float e = __expf(fmaf(ns, v.x, 1.0f));
        float d = __fdividef(1.0f, 1.0f + e);
        p0.x = d; p1.x = 1.0f - d;
    }
    {
        float e = __expf(fmaf(ns, v.y, 1.0f));
        float d = __fdividef(1.0f, 1.0f + e);
        p0.y = d; p1.y = 1.0f - d;
    }
    {
        float e = __expf(fmaf(ns, v.z, 1.0f));
        float d = __fdividef(1.0f, 1.0f + e);
        p0.z = d; p1.z = 1.0f - d;
    }
    {
        float e = __expf(fmaf(ns, v.w, 1.0f));
        float d = __fdividef(1.0f, 1.0f + e);
        p0.w = d; p1.w = 1.0f - d;
    }
    __stcs(&o0[i], p0);
    __stcs(&o1[i], p1);
}

// ---------------------------------------------------------------------------
// Launch. d_in[0] = image_irr (16M fp32), d_in[1] = image_vis (dead in the
// reference — never read). d_out = msks[0] then msks[1], concatenated.
// ---------------------------------------------------------------------------
extern "C" void kernel_launch(void* const* d_in, const int* in_sizes, int n_in,
                              void* d_out, int out_size) {
    const float* irr = (const float*)d_in[0];
    float* out = (float*)d_out;

    dim3 sgrid(SBLK, NB, 1);
    wsm_stats_kernel<<<sgrid, 256>>>(irr);

    wsm_flag_kernel<<<NB, 32>>>();

    wsm_out_kernel<<<N4 / 256, 256>>>(irr, out);
}

// round 13
// speedup vs baseline: 1.5268x; 1.0374x over previous
#include <cuda_runtime.h>

// Problem shape (fixed by the reference): (16, 1, 1024, 1024) fp32.
#define NB     16
#define HW     (1024 * 1024)
#define TOTAL  (NB * HW)
#define N4     (TOTAL / 4)
#define HW4    (HW / 4)          // 262144 float4 per batch
#define FT     1024              // threads in the flag kernel

// Scratch (allocation-free rule: __device__ global). Plain overwrite every
// replay -> deterministic, graph-safe, no zeroing needed.
__device__ float g_nscale[NB];   // -2 * scale  (scale in {0,1})

// ---------------------------------------------------------------------------
// helpers
// ---------------------------------------------------------------------------

// jnp.histogram bin over range (0,255), 256 bins, last edge inclusive.
// Monotone non-decreasing in v, so bin(min v)/bin(max v) give min/max bin.
__device__ __forceinline__ int bin_of(float v) {
    int b = (int)(v * (256.0f / 255.0f));
    return b > 255 ? 255 : b;
}

__device__ __forceinline__ void acc_elem(float x, float& mnv, float& mxv,
                                         float& mnvv, float& mxvv) {
    float v = x * 255.0f;                          // identical to reference mi
    bool inr = (v >= 0.0f) && (v <= 255.0f);
    float r = rintf(v);                            // round-half-even == jnp.round
    bool val = inr && (v == r);                    // valid mask pixel
    if (inr) { mnv  = fminf(mnv,  v); mxv  = fmaxf(mxv,  v); }
    if (val) { mnvv = fminf(mnvv, v); mxvv = fmaxf(mxvv, v); }
}

__device__ __forceinline__ float warp_minf(float v) {
#pragma unroll
    for (int o = 16; o; o >>= 1) v = fminf(v, __shfl_xor_sync(0xffffffffu, v, o));
    return v;
}
__device__ __forceinline__ float warp_maxf(float v) {
#pragma unroll
    for (int o = 16; o; o >>= 1) v = fmaxf(v, __shfl_xor_sync(0xffffffffu, v, o));
    return v;
}

// ---------------------------------------------------------------------------
// K1 (fused flag kernel): ONE block per batch.
//
// flag = 1 iff mask.max() > 0, where mask_output[r] = sum_j |r-j|*hist[j]:
//   - hist empty                      -> flag 0
//   - >= 2 distinct occupied bins     -> mask_output[r] > 0 for ALL r
//                                        -> flag = (any valid pixel)
//   - exactly 1 occupied bin b0       -> zero only at r = b0
//                                        -> flag = exists valid idx != b0
//
// Fast path: each thread checks its own 4 sampled elements for
// (>=2 distinct bins) && (>=1 valid pixel). That conjunction, observed
// ANYWHERE, implies the global flag is 1 (both facts are monotone in the
// data). One __syncthreads_or combines 1024 threads; on success the block
// writes g_nscale and exits after reading only 16 KB.
// Fallback (any input where no single thread determines): full scan of the
// batch with exact min/max tracking -> exact flag. Slow but correct.
// ---------------------------------------------------------------------------
__global__ void __launch_bounds__(FT) wsm_flag_kernel(const float* __restrict__ irr) {
    const int b = blockIdx.x;
    const float4* __restrict__ in4 =
        reinterpret_cast<const float4*>(irr + (size_t)b * HW);
    const int t = threadIdx.x;

    // ---- phase 1: strided 16 KB sample, per-thread determination ----
    int det;
    {
        // stride the sample across the batch so clustered images still hit
        float4 v4 = in4[t * (HW4 / FT)];
        float a = v4.x * 255.0f, bb = v4.y * 255.0f;
        float c = v4.z * 255.0f, d = v4.w * 255.0f;

        bool ia = (a >= 0.0f) & (a <= 255.0f), ib = (bb >= 0.0f) & (bb <= 255.0f);
        bool ic = (c >= 0.0f) & (c <= 255.0f), id = (d >= 0.0f) & (d <= 255.0f);
        int ba = ia ? bin_of(a) : -1, bq = ib ? bin_of(bb) : -1;
        int bc = ic ? bin_of(c) : -1, bd = id ? bin_of(d) : -1;

        // >=2 distinct occupied bins among this thread's in-range elems
        int mx = max(max(ba, bq), max(bc, bd));
        int mn = 257;
        if (ba >= 0) mn = min(mn, ba);
        if (bq >= 0) mn = min(mn, bq);
        if (bc >= 0) mn = min(mn, bc);
        if (bd >= 0) mn = min(mn, bd);
        bool two_bins = (mx >= 0) && (mn != mx);

        bool any_valid = (ia && a == rintf(a)) || (ib && bb == rintf(bb)) ||
                         (ic && c == rintf(c)) || (id && d == rintf(d));
        det = (two_bins && any_valid) ? 1 : 0;
    }
    if (__syncthreads_or(det)) {
        if (t == 0) g_nscale[b] = -2.0f;     // flag = 1  ->  ns = -2*scale
        return;
    }

    // ---- fallback: exact full scan of this batch (correctness path) ----
    float mnv = 1e30f, mxv = -1e30f;     // in-range v  (empty: mnv > mxv)
    float mnvv = 1e30f, mxvv = -1e30f;   // valid v     (empty: mnvv > mxvv)
    for (int i = t; i < HW4; i += FT) {
        float4 v4 = in4[i];
        acc_elem(v4.x, mnv, mxv, mnvv, mxvv);
        acc_elem(v4.y, mnv, mxv, mnvv, mxvv);
        acc_elem(v4.z, mnv, mxv, mnvv, mxvv);
        acc_elem(v4.w, mnv, mxv, mnvv, mxvv);
    }
    // block reduce (32 warps)
    __shared__ float sm[4][32];
    float a = warp_minf(mnv), bx = warp_maxf(mxv);
    float c = warp_minf(mnvv), d = warp_maxf(mxvv);
    const int w = t >> 5, l = t & 31;
    if (l == 0) { sm[0][w] = a; sm[1][w] = bx; sm[2][w] = c; sm[3][w] = d; }
    __syncthreads();
    if (t == 0) {
        a = sm[0][0]; bx = sm[1][0]; c = sm[2][0]; d = sm[3][0];
#pragma unroll
        for (int j = 1; j < 32; j++) {
            a = fminf(a, sm[0][j]); bx = fmaxf(bx, sm[1][j]);
            c = fminf(c, sm[2][j]); d = fmaxf(d, sm[3][j]);
        }
        int flag;
        const bool any_range = (a <= bx);
        const bool any_valid = (c <= d);
        if (!any_range) flag = 0;                            // hist empty
        else {
            int mnb = bin_of(a), mxb = bin_of(bx);
            if (mnb != mxb) flag = any_valid ? 1 : 0;        // >=2 bins
            else {
                int mni = (int)c, mxi = (int)d;              // exact ints
                flag = (any_valid && (mni != mnb || mxi != mnb)) ? 1 : 0;
            }
        }
        g_nscale[b] = flag ? -2.0f : 0.0f;
    }
}

// ---------------------------------------------------------------------------
// K3: elementwise output (the real bandwidth cost, ~192 MB).
//   m    = scale * v
//   out0 = 1/(1 + e^(1-2m)),  out1 = 1 - out0
// ILP=2: both float4 loaded up front (MLP batching), then compute, then 4
// streaming stores. Nothing is reused -> .cs on all traffic.
// ---------------------------------------------------------------------------
__device__ __forceinline__ void sm_pair(float ns, const float4& v,
                                        float4& p0, float4& p1) {
    {
        float e = __expf(fmaf(ns, v.x, 1.0f));
        float dd = __fdividef(1.0f, 1.0f + e);
        p0.x = dd; p1.x = 1.0f - dd;
    }
    {
        float e = __expf(fmaf(ns, v.y, 1.0f));
        float dd = __fdividef(1.0f, 1.0f + e);
        p0.y = dd; p1.y = 1.0f - dd;
    }
    {
        float e = __expf(fmaf(ns, v.z, 1.0f));
        float dd = __fdividef(1.0f, 1.0f + e);
        p0.z = dd; p1.z = 1.0f - dd;
    }
    {
        float e = __expf(fmaf(ns, v.w, 1.0f));
        float dd = __fdividef(1.0f, 1.0f + e);
        p0.w = dd; p1.w = 1.0f - dd;
    }
}

__global__ void __launch_bounds__(256) wsm_out_kernel(const float* __restrict__ irr,
                                                      float* __restrict__ out) {
    // Each block covers 512 consecutive float4 (2 per thread).
    // HW4/512 = 512 blocks per batch  ->  batch = blockIdx.x >> 9.
    const int i0 = blockIdx.x * 512 + threadIdx.x;
    const int i1 = i0 + 256;
    const float ns = g_nscale[blockIdx.x >> 9];

    const float4* __restrict__ in4 = reinterpret_cast<const float4*>(irr);
    float4* __restrict__ o0 = reinterpret_cast<float4*>(out);
    float4* __restrict__ o1 = reinterpret_cast<float4*>(out + (size_t)TOTAL);

    float4 va = __ldcs(&in4[i0]);
    float4 vb = __ldcs(&in4[i1]);

    float4 a0, a1, b0, b1;
    sm_pair(ns, va, a0, a1);
    sm_pair(ns, vb, b0, b1);

    __stcs(&o0[i0], a0);
    __stcs(&o0[i1], b0);
    __stcs(&o1[i0], a1);
    __stcs(&o1[i1], b1);
}

// ---------------------------------------------------------------------------
// Launch. d_in[0] = image_irr (16M fp32), d_in[1] = image_vis (dead in the
// reference — never read). d_out = msks[0] then msks[1], concatenated.
// ---------------------------------------------------------------------------
extern "C" void kernel_launch(void* const* d_in, const int* in_sizes, int n_in,
                              void* d_out, int out_size) {
    const float* irr = (const float*)d_in[0];
    float* out = (float*)d_out;

    wsm_flag_kernel<<<NB, FT>>>(irr);
    wsm_out_kernel<<<N4 / 512, 256>>>(irr, out);
}

// round 14
// speedup vs baseline: 1.5360x; 1.0060x over previous
#include <cuda_runtime.h>

// Problem shape (fixed by the reference): (16, 1, 1024, 1024) fp32.
#define NB     16
#define HW     (1024 * 1024)
#define TOTAL  (NB * HW)
#define N4     (TOTAL / 4)
#define HW4    (HW / 4)          // 262144 float4 per batch
#define FT     1024              // threads in the flag kernel

// Scratch (allocation-free rule: __device__ global). Plain overwrite every
// replay -> deterministic, graph-safe, no zeroing needed.
__device__ float g_nscale[NB];   // -2 * scale  (scale in {0,1})

// ---------------------------------------------------------------------------
// helpers
// ---------------------------------------------------------------------------

// jnp.histogram bin over range (0,255), 256 bins, last edge inclusive.
// Monotone non-decreasing in v, so bin(min v)/bin(max v) give min/max bin.
__device__ __forceinline__ int bin_of(float v) {
    int b = (int)(v * (256.0f / 255.0f));
    return b > 255 ? 255 : b;
}

__device__ __forceinline__ void acc_elem(float x, float& mnv, float& mxv,
                                         float& mnvv, float& mxvv) {
    float v = x * 255.0f;                          // identical to reference mi
    bool inr = (v >= 0.0f) && (v <= 255.0f);
    float r = rintf(v);                            // round-half-even == jnp.round
    bool val = inr && (v == r);                    // valid mask pixel
    if (inr) { mnv  = fminf(mnv,  v); mxv  = fmaxf(mxv,  v); }
    if (val) { mnvv = fminf(mnvv, v); mxvv = fmaxf(mxvv, v); }
}

__device__ __forceinline__ float warp_minf(float v) {
#pragma unroll
    for (int o = 16; o; o >>= 1) v = fminf(v, __shfl_xor_sync(0xffffffffu, v, o));
    return v;
}
__device__ __forceinline__ float warp_maxf(float v) {
#pragma unroll
    for (int o = 16; o; o >>= 1) v = fmaxf(v, __shfl_xor_sync(0xffffffffu, v, o));
    return v;
}

// ---------------------------------------------------------------------------
// K1 (flag kernel): ONE block per batch.
//
// flag = 1 iff mask.max() > 0, where mask_output[r] = sum_j |r-j|*hist[j]:
//   - hist empty                      -> flag 0
//   - >= 2 distinct occupied bins     -> mask_output[r] > 0 for ALL r
//                                        -> flag = (any valid pixel)
//   - exactly 1 occupied bin b0       -> zero only at r = b0
//                                        -> flag = exists valid idx != b0
//
// Fast path: each thread checks its own 4 sampled elements for
// (>=2 distinct bins) && (>=1 valid pixel); observed anywhere, that implies
// flag=1 globally (both facts are monotone in the data). One __syncthreads_or
// combines 1024 threads; on success the block exits after reading 16 KB.
// Fallback: exact full scan with min/max tracking — correct for any input.
// ---------------------------------------------------------------------------
__global__ void __launch_bounds__(FT) wsm_flag_kernel(const float* __restrict__ irr) {
    const int b = blockIdx.x;
    const float4* __restrict__ in4 =
        reinterpret_cast<const float4*>(irr + (size_t)b * HW);
    const int t = threadIdx.x;

    // ---- phase 1: strided 16 KB sample, per-thread determination ----
    int det;
    {
        float4 v4 = in4[t * (HW4 / FT)];
        float a = v4.x * 255.0f, bb = v4.y * 255.0f;
        float c = v4.z * 255.0f, d = v4.w * 255.0f;

        bool ia = (a >= 0.0f) & (a <= 255.0f), ib = (bb >= 0.0f) & (bb <= 255.0f);
        bool ic = (c >= 0.0f) & (c <= 255.0f), id = (d >= 0.0f) & (d <= 255.0f);
        int ba = ia ? bin_of(a) : -1, bq = ib ? bin_of(bb) : -1;
        int bc = ic ? bin_of(c) : -1, bd = id ? bin_of(d) : -1;

        int mx = max(max(ba, bq), max(bc, bd));
        int mn = 257;
        if (ba >= 0) mn = min(mn, ba);
        if (bq >= 0) mn = min(mn, bq);
        if (bc >= 0) mn = min(mn, bc);
        if (bd >= 0) mn = min(mn, bd);
        bool two_bins = (mx >= 0) && (mn != mx);

        bool any_valid = (ia && a == rintf(a)) || (ib && bb == rintf(bb)) ||
                         (ic && c == rintf(c)) || (id && d == rintf(d));
        det = (two_bins && any_valid) ? 1 : 0;
    }
    if (__syncthreads_or(det)) {
        if (t == 0) g_nscale[b] = -2.0f;     // flag = 1  ->  ns = -2*scale
        return;
    }

    // ---- fallback: exact full scan of this batch (correctness path) ----
    float mnv = 1e30f, mxv = -1e30f;     // in-range v  (empty: mnv > mxv)
    float mnvv = 1e30f, mxvv = -1e30f;   // valid v     (empty: mnvv > mxvv)
    for (int i = t; i < HW4; i += FT) {
        float4 v4 = in4[i];
        acc_elem(v4.x, mnv, mxv, mnvv, mxvv);
        acc_elem(v4.y, mnv, mxv, mnvv, mxvv);
        acc_elem(v4.z, mnv, mxv, mnvv, mxvv);
        acc_elem(v4.w, mnv, mxv, mnvv, mxvv);
    }
    __shared__ float sm[4][32];
    float a = warp_minf(mnv), bx = warp_maxf(mxv);
    float c = warp_minf(mnvv), d = warp_maxf(mxvv);
    const int w = t >> 5, l = t & 31;
    if (l == 0) { sm[0][w] = a; sm[1][w] = bx; sm[2][w] = c; sm[3][w] = d; }
    __syncthreads();
    if (t == 0) {
        a = sm[0][0]; bx = sm[1][0]; c = sm[2][0]; d = sm[3][0];
#pragma unroll
        for (int j = 1; j < 32; j++) {
            a = fminf(a, sm[0][j]); bx = fmaxf(bx, sm[1][j]);
            c = fminf(c, sm[2][j]); d = fmaxf(d, sm[3][j]);
        }
        int flag;
        const bool any_range = (a <= bx);
        const bool any_valid = (c <= d);
        if (!any_range) flag = 0;                            // hist empty
        else {
            int mnb = bin_of(a), mxb = bin_of(bx);
            if (mnb != mxb) flag = any_valid ? 1 : 0;        // >=2 bins
            else {
                int mni = (int)c, mxi = (int)d;              // exact ints
                flag = (any_valid && (mni != mnb || mxi != mnb)) ? 1 : 0;
            }
        }
        g_nscale[b] = flag ? -2.0f : 0.0f;
    }
}

// ---------------------------------------------------------------------------
// K3: elementwise output (write-drain-bound stream, ~144 MB DRAM/iter).
//   m    = scale * v
//   out0 = 1/(1 + e^(1-2m)),  out1 = 1 - out0
// ILP=4, strided (+0,+256,+512,+768): 4 fully-coalesced front-batched LDG.128
// per thread. Loads use default caching (input stays L2-resident across graph
// replays — observed: DRAM traffic ~= writes only). Stores stay .cs so the
// 128 MB output stream is evict-first and doesn't displace the input in L2.
// ---------------------------------------------------------------------------
__device__ __forceinline__ void sm_pair(float ns, const float4& v,
                                        float4& p0, float4& p1) {
    {
        float e = __expf(fmaf(ns, v.x, 1.0f));
        float dd = __fdividef(1.0f, 1.0f + e);
        p0.x = dd; p1.x = 1.0f - dd;
    }
    {
        float e = __expf(fmaf(ns, v.y, 1.0f));
        float dd = __fdividef(1.0f, 1.0f + e);
        p0.y = dd; p1.y = 1.0f - dd;
    }
    {
        float e = __expf(fmaf(ns, v.z, 1.0f));
        float dd = __fdividef(1.0f, 1.0f + e);
        p0.z = dd; p1.z = 1.0f - dd;
    }
    {
        float e = __expf(fmaf(ns, v.w, 1.0f));
        float dd = __fdividef(1.0f, 1.0f + e);
        p0.w = dd; p1.w = 1.0f - dd;
    }
}

__global__ void __launch_bounds__(256) wsm_out_kernel(const float* __restrict__ irr,
                                                      float* __restrict__ out) {
    // Each block covers 1024 consecutive float4 (4 per thread, stride 256).
    // HW4/1024 = 256 blocks per batch -> batch = blockIdx.x >> 8.
    const int base = blockIdx.x * 1024 + threadIdx.x;
    const float ns = g_nscale[blockIdx.x >> 8];

    const float4* __restrict__ in4 = reinterpret_cast<const float4*>(irr);
    float4* __restrict__ o0 = reinterpret_cast<float4*>(out);
    float4* __restrict__ o1 = reinterpret_cast<float4*>(out + (size_t)TOTAL);

    // front-batched loads (MLP_p1 = 4)
    float4 va = __ldg(&in4[base]);
    float4 vb = __ldg(&in4[base + 256]);
    float4 vc = __ldg(&in4[base + 512]);
    float4 vd = __ldg(&in4[base + 768]);

    float4 a0, a1, b0, b1, c0, c1, d0, d1;
    sm_pair(ns, va, a0, a1);
    sm_pair(ns, vb, b0, b1);
    sm_pair(ns, vc, c0, c1);
    sm_pair(ns, vd, d0, d1);

    __stcs(&o0[base],       a0);
    __stcs(&o0[base + 256], b0);
    __stcs(&o0[base + 512], c0);
    __stcs(&o0[base + 768], d0);
    __stcs(&o1[base],       a1);
    __stcs(&o1[base + 256], b1);
    __stcs(&o1[base + 512], c1);
    __stcs(&o1[base + 768], d1);
}

// ---------------------------------------------------------------------------
// Launch. d_in[0] = image_irr (16M fp32), d_in[1] = image_vis (dead in the
// reference — never read). d_out = msks[0] then msks[1], concatenated.
// ---------------------------------------------------------------------------
extern "C" void kernel_launch(void* const* d_in, const int* in_sizes, int n_in,
                              void* d_out, int out_size) {
    const float* irr = (const float*)d_in[0];
    float* out = (float*)d_out;

    wsm_flag_kernel<<<NB, FT>>>(irr);
    wsm_out_kernel<<<N4 / 1024, 256>>>(irr, out);
}

// round 15
// speedup vs baseline: 1.6221x; 1.0561x over previous
#include <cuda_runtime.h>

// Problem shape (fixed by the reference): (16, 1, 1024, 1024) fp32.
#define NB     16
#define HW     (1024 * 1024)
#define TOTAL  (NB * HW)
#define N4     (TOTAL / 4)
#define HW4    (HW / 4)          // 262144 float4 per batch

// ---------------------------------------------------------------------------
// helpers
// ---------------------------------------------------------------------------

// jnp.histogram bin over range (0,255), 256 bins, last edge inclusive.
// Monotone non-decreasing in v, so bin(min v)/bin(max v) give min/max bin.
__device__ __forceinline__ int bin_of(float v) {
    int b = (int)(v * (256.0f / 255.0f));
    return b > 255 ? 255 : b;
}

// Fast-path determination accumulator (branchless).
__device__ __forceinline__ void det_elem(float x, float& mnv, float& mxv,
                                         bool& anyv) {
    float v = x * 255.0f;                          // identical to reference mi
    bool inr = (v >= 0.0f) && (v <= 255.0f);
    mnv = fminf(mnv, inr ? v :  1e30f);
    mxv = fmaxf(mxv, inr ? v : -1e30f);
    anyv = anyv || (inr && (v == rintf(v)));       // rintf == jnp.round (half-even)
}

// Exact-path accumulator (fallback full scan).
__device__ __forceinline__ void acc_elem(float x, float& mnv, float& mxv,
                                         float& mnvv, float& mxvv) {
    float v = x * 255.0f;
    bool inr = (v >= 0.0f) && (v <= 255.0f);
    float r = rintf(v);
    bool val = inr && (v == r);
    if (inr) { mnv  = fminf(mnv,  v); mxv  = fmaxf(mxv,  v); }
    if (val) { mnvv = fminf(mnvv, v); mxvv = fmaxf(mxvv, v); }
}

__device__ __forceinline__ float warp_minf(float v) {
#pragma unroll
    for (int o = 16; o; o >>= 1) v = fminf(v, __shfl_xor_sync(0xffffffffu, v, o));
    return v;
}
__device__ __forceinline__ float warp_maxf(float v) {
#pragma unroll
    for (int o = 16; o; o >>= 1) v = fmaxf(v, __shfl_xor_sync(0xffffffffu, v, o));
    return v;
}

__device__ __forceinline__ void sm_pair(float ns, const float4& v,
                                        float4& p0, float4& p1) {
    {
        float e = __expf(fmaf(ns, v.x, 1.0f));
        float dd = __fdividef(1.0f, 1.0f + e);
        p0.x = dd; p1.x = 1.0f - dd;
    }
    {
        float e = __expf(fmaf(ns, v.y, 1.0f));
        float dd = __fdividef(1.0f, 1.0f + e);
        p0.y = dd; p1.y = 1.0f - dd;
    }
    {
        float e = __expf(fmaf(ns, v.z, 1.0f));
        float dd = __fdividef(1.0f, 1.0f + e);
        p0.z = dd; p1.z = 1.0f - dd;
    }
    {
        float e = __expf(fmaf(ns, v.w, 1.0f));
        float dd = __fdividef(1.0f, 1.0f + e);
        p0.w = dd; p1.w = 1.0f - dd;
    }
}

// ---------------------------------------------------------------------------
// Single fused kernel.
//
// flag(batch) = 1 iff mask.max() > 0, where mask_output[r] = sum_j |r-j|*hist[j]:
//   - hist empty                   -> 0
//   - >= 2 distinct occupied bins  -> mask_output > 0 everywhere -> (any valid)
//   - exactly 1 occupied bin b0    -> zero only at r=b0 -> (valid idx != b0)
//
// Fast path (no extra memory traffic): each thread derives, from the 16
// elements it already loaded for the output computation, whether they span
// >= 2 occupied bins AND contain >= 1 valid (integer, in-range) pixel. That
// conjunction observed ANYWHERE implies the global flag is 1 (both facts are
// monotone under adding data). One __syncthreads_or combines the block.
//
// Fallback (block could not self-determine — only near-constant or integer-
// free images): the block performs an exact full scan of its batch tracking
// min/max in-range value and min/max valid value, which resolve all three
// cases exactly. Every block of a batch computes the identical flag, so the
// output is consistent and correct for ANY input (just slower on adversarial
// data). Deterministic; no cross-kernel scratch at all.
//
//   m    = scale * v
//   out0 = 1/(1 + e^(1-2m)),  out1 = 1 - out0        (ns = -2*scale)
//
// ILP=4 front-batched LDG.128; stores .cs (128 MB evict-first write stream,
// measured wall ~4.9 TB/s — DRAM-write-bound, compute has large headroom).
// ---------------------------------------------------------------------------
__global__ void __launch_bounds__(256) wsm_kernel(const float* __restrict__ irr,
                                                  float* __restrict__ out) {
    // Each block covers 1024 consecutive float4 (4 per thread, stride 256).
    // 256 blocks per batch -> batch = blockIdx.x >> 8.
    const int base = blockIdx.x * 1024 + threadIdx.x;
    const int b = blockIdx.x >> 8;

    const float4* __restrict__ in4 = reinterpret_cast<const float4*>(irr);
    float4* __restrict__ o0 = reinterpret_cast<float4*>(out);
    float4* __restrict__ o1 = reinterpret_cast<float4*>(out + (size_t)TOTAL);

    // front-batched loads (MLP_p1 = 4)
    float4 va = __ldg(&in4[base]);
    float4 vb = __ldg(&in4[base + 256]);
    float4 vc = __ldg(&in4[base + 512]);
    float4 vd = __ldg(&in4[base + 768]);

    // ---- flag determination from the already-loaded data ----
    float mnv = 1e30f, mxv = -1e30f;
    bool anyv = false;
    det_elem(va.x, mnv, mxv, anyv); det_elem(va.y, mnv, mxv, anyv);
    det_elem(va.z, mnv, mxv, anyv); det_elem(va.w, mnv, mxv, anyv);
    det_elem(vb.x, mnv, mxv, anyv); det_elem(vb.y, mnv, mxv, anyv);
    det_elem(vb.z, mnv, mxv, anyv); det_elem(vb.w, mnv, mxv, anyv);
    det_elem(vc.x, mnv, mxv, anyv); det_elem(vc.y, mnv, mxv, anyv);
    det_elem(vc.z, mnv, mxv, anyv); det_elem(vc.w, mnv, mxv, anyv);
    det_elem(vd.x, mnv, mxv, anyv); det_elem(vd.y, mnv, mxv, anyv);
    det_elem(vd.z, mnv, mxv, anyv); det_elem(vd.w, mnv, mxv, anyv);

    int det = (mnv <= mxv) && anyv && (bin_of(mnv) != bin_of(mxv));

    float ns;
    if (__syncthreads_or(det)) {
        ns = -2.0f;                                  // flag = 1
    } else {
        // ---- fallback: exact full scan of this batch (rare; correct always) ----
        const float4* __restrict__ bat4 =
            reinterpret_cast<const float4*>(irr + (size_t)b * HW);
        float fmn = 1e30f, fmx = -1e30f;             // in-range v
        float gmn = 1e30f, gmx = -1e30f;             // valid v
        for (int i = threadIdx.x; i < HW4; i += 256) {
            float4 v4 = bat4[i];
            acc_elem(v4.x, fmn, fmx, gmn, gmx);
            acc_elem(v4.y, fmn, fmx, gmn, gmx);
            acc_elem(v4.z, fmn, fmx, gmn, gmx);
            acc_elem(v4.w, fmn, fmx, gmn, gmx);
        }
        __shared__ float sm[4][8];
        __shared__ float s_ns;
        float a = warp_minf(fmn), bx = warp_maxf(fmx);
        float c = warp_minf(gmn), d = warp_maxf(gmx);
        const int w = threadIdx.x >> 5, l = threadIdx.x & 31;
        if (l == 0) { sm[0][w] = a; sm[1][w] = bx; sm[2][w] = c; sm[3][w] = d; }
        __syncthreads();
        if (threadIdx.x == 0) {
            a = sm[0][0]; bx = sm[1][0]; c = sm[2][0]; d = sm[3][0];
#pragma unroll
            for (int j = 1; j < 8; j++) {
                a = fminf(a, sm[0][j]); bx = fmaxf(bx, sm[1][j]);
                c = fminf(c, sm[2][j]); d = fmaxf(d, sm[3][j]);
            }
            int flag;
            const bool any_range = (a <= bx);
            const bool any_valid = (c <= d);
            if (!any_range) flag = 0;                        // hist empty
            else {
                int mnb = bin_of(a), mxb = bin_of(bx);
                if (mnb != mxb) flag = any_valid ? 1 : 0;    // >= 2 bins
                else {
                    int mni = (int)c, mxi = (int)d;          // exact ints
                    flag = (any_valid && (mni != mnb || mxi != mnb)) ? 1 : 0;
                }
            }
            s_ns = flag ? -2.0f : 0.0f;
        }
        __syncthreads();
        ns = s_ns;
    }

    // ---- output ----
    float4 a0, a1, b0, b1, c0, c1, d0, d1;
    sm_pair(ns, va, a0, a1);
    sm_pair(ns, vb, b0, b1);
    sm_pair(ns, vc, c0, c1);
    sm_pair(ns, vd, d0, d1);

    __stcs(&o0[base],       a0);
    __stcs(&o0[base + 256], b0);
    __stcs(&o0[base + 512], c0);
    __stcs(&o0[base + 768], d0);
    __stcs(&o1[base],       a1);
    __stcs(&o1[base + 256], b1);
    __stcs(&o1[base + 512], c1);
    __stcs(&o1[base + 768], d1);
}

// ---------------------------------------------------------------------------
// Launch. d_in[0] = image_irr (16M fp32), d_in[1] = image_vis (dead in the
// reference — never read). d_out = msks[0] then msks[1], concatenated.
// ---------------------------------------------------------------------------
extern "C" void kernel_launch(void* const* d_in, const int* in_sizes, int n_in,
                              void* d_out, int out_size) {
    const float* irr = (const float*)d_in[0];
    float* out = (float*)d_out;

    wsm_kernel<<<N4 / 1024, 256>>>(irr, out);
}

// round 16
// speedup vs baseline: 1.6265x; 1.0027x over previous
#include <cuda_runtime.h>

// Problem shape (fixed by the reference): (16, 1, 1024, 1024) fp32.
#define NB     16
#define HW     (1024 * 1024)
#define TOTAL  (NB * HW)
#define N4     (TOTAL / 4)
#define HW4    (HW / 4)          // 262144 float4 per batch

// ---------------------------------------------------------------------------
// helpers
// ---------------------------------------------------------------------------

// jnp.histogram bin over range (0,255), 256 bins, last edge inclusive.
// Monotone non-decreasing in v, so bin(min v)/bin(max v) give min/max bin.
__device__ __forceinline__ int bin_of(float v) {
    int b = (int)(v * (256.0f / 255.0f));
    return b > 255 ? 255 : b;
}

// Fast-path determination accumulator (branchless).
__device__ __forceinline__ void det_elem(float x, float& mnv, float& mxv,
                                         bool& anyv) {
    float v = x * 255.0f;                          // identical to reference mi
    bool inr = (v >= 0.0f) && (v <= 255.0f);
    mnv = fminf(mnv, inr ? v :  1e30f);
    mxv = fmaxf(mxv, inr ? v : -1e30f);
    anyv = anyv || (inr && (v == rintf(v)));       // rintf == jnp.round (half-even)
}

// Exact-path accumulator (fallback full scan).
__device__ __forceinline__ void acc_elem(float x, float& mnv, float& mxv,
                                         float& mnvv, float& mxvv) {
    float v = x * 255.0f;
    bool inr = (v >= 0.0f) && (v <= 255.0f);
    float r = rintf(v);
    bool val = inr && (v == r);
    if (inr) { mnv  = fminf(mnv,  v); mxv  = fmaxf(mxv,  v); }
    if (val) { mnvv = fminf(mnvv, v); mxvv = fmaxf(mxvv, v); }
}

__device__ __forceinline__ float warp_minf(float v) {
#pragma unroll
    for (int o = 16; o; o >>= 1) v = fminf(v, __shfl_xor_sync(0xffffffffu, v, o));
    return v;
}
__device__ __forceinline__ float warp_maxf(float v) {
#pragma unroll
    for (int o = 16; o; o >>= 1) v = fmaxf(v, __shfl_xor_sync(0xffffffffu, v, o));
    return v;
}

__device__ __forceinline__ void sm_pair(float ns, const float4& v,
                                        float4& p0, float4& p1) {
    {
        float e = __expf(fmaf(ns, v.x, 1.0f));
        float dd = __fdividef(1.0f, 1.0f + e);
        p0.x = dd; p1.x = 1.0f - dd;
    }
    {
        float e = __expf(fmaf(ns, v.y, 1.0f));
        float dd = __fdividef(1.0f, 1.0f + e);
        p0.y = dd; p1.y = 1.0f - dd;
    }
    {
        float e = __expf(fmaf(ns, v.z, 1.0f));
        float dd = __fdividef(1.0f, 1.0f + e);
        p0.z = dd; p1.z = 1.0f - dd;
    }
    {
        float e = __expf(fmaf(ns, v.w, 1.0f));
        float dd = __fdividef(1.0f, 1.0f + e);
        p0.w = dd; p1.w = 1.0f - dd;
    }
}

// ---------------------------------------------------------------------------
// Single fused kernel.
//
// flag(batch) = 1 iff mask.max() > 0, where mask_output[r] = sum_j |r-j|*hist[j]:
//   - hist empty                   -> 0
//   - >= 2 distinct occupied bins  -> mask_output > 0 everywhere -> (any valid)
//   - exactly 1 occupied bin b0    -> zero only at r=b0 -> (valid idx != b0)
//
// Fast path (no extra memory traffic): each thread checks only its FIRST
// float4 (4 elements) for ">= 2 occupied bins AND >= 1 valid pixel"; the
// block-level __syncthreads_or still aggregates 1024 elements of evidence.
// Both facts are monotone under adding data, so local evidence anywhere
// implies the global flag is 1. Keeping vb/vc/vd out of the determination
// dataflow shortens live ranges (R15 post-mortem: 16-elem det cost 46 regs,
// occ 55%).
//
// Fallback (block could not self-determine — only near-constant or integer-
// free images): exact full scan of the batch with min/max tracking, resolving
// all three cases exactly. Every block of a batch computes the identical
// flag -> consistent, correct for ANY input, just slower on adversarial data.
//
//   m    = scale * v
//   out0 = 1/(1 + e^(1-2m)),  out1 = 1 - out0        (ns = -2*scale)
//
// ILP=4 front-batched LDG.128; stores .cs (128 MB evict-first write stream,
// measured ~4.9 TB/s — DRAM-write-bound; compute has headroom).
// ---------------------------------------------------------------------------
__global__ void __launch_bounds__(256, 6) wsm_kernel(const float* __restrict__ irr,
                                                     float* __restrict__ out) {
    // Each block covers 1024 consecutive float4 (4 per thread, stride 256).
    // 256 blocks per batch -> batch = blockIdx.x >> 8.
    const int base = blockIdx.x * 1024 + threadIdx.x;
    const int b = blockIdx.x >> 8;

    const float4* __restrict__ in4 = reinterpret_cast<const float4*>(irr);
    float4* __restrict__ o0 = reinterpret_cast<float4*>(out);
    float4* __restrict__ o1 = reinterpret_cast<float4*>(out + (size_t)TOTAL);

    // front-batched loads (MLP_p1 = 4)
    float4 va = __ldg(&in4[base]);
    float4 vb = __ldg(&in4[base + 256]);
    float4 vc = __ldg(&in4[base + 512]);
    float4 vd = __ldg(&in4[base + 768]);

    // ---- flag determination from va only (4 elems/thread, 1024/block) ----
    int det;
    {
        float mnv = 1e30f, mxv = -1e30f;
        bool anyv = false;
        det_elem(va.x, mnv, mxv, anyv);
        det_elem(va.y, mnv, mxv, anyv);
        det_elem(va.z, mnv, mxv, anyv);
        det_elem(va.w, mnv, mxv, anyv);
        det = (mnv <= mxv) && anyv && (bin_of(mnv) != bin_of(mxv));
    }

    float ns;
    if (__syncthreads_or(det)) {
        ns = -2.0f;                                  // flag = 1
    } else {
        // ---- fallback: exact full scan of this batch (rare; correct always) ----
        const float4* __restrict__ bat4 =
            reinterpret_cast<const float4*>(irr + (size_t)b * HW);
        float fmn = 1e30f, fmx = -1e30f;             // in-range v
        float gmn = 1e30f, gmx = -1e30f;             // valid v
        for (int i = threadIdx.x; i < HW4; i += 256) {
            float4 v4 = bat4[i];
            acc_elem(v4.x, fmn, fmx, gmn, gmx);
            acc_elem(v4.y, fmn, fmx, gmn, gmx);
            acc_elem(v4.z, fmn, fmx, gmn, gmx);
            acc_elem(v4.w, fmn, fmx, gmn, gmx);
        }
        __shared__ float sm[4][8];
        __shared__ float s_ns;
        float a = warp_minf(fmn), bx = warp_maxf(fmx);
        float c = warp_minf(gmn), d = warp_maxf(gmx);
        const int w = threadIdx.x >> 5, l = threadIdx.x & 31;
        if (l == 0) { sm[0][w] = a; sm[1][w] = bx; sm[2][w] = c; sm[3][w] = d; }
        __syncthreads();
        if (threadIdx.x == 0) {
            a = sm[0][0]; bx = sm[1][0]; c = sm[2][0]; d = sm[3][0];
#pragma unroll
            for (int j = 1; j < 8; j++) {
                a = fminf(a, sm[0][j]); bx = fmaxf(bx, sm[1][j]);
                c = fminf(c, sm[2][j]); d = fmaxf(d, sm[3][j]);
            }
            int flag;
            const bool any_range = (a <= bx);
            const bool any_valid = (c <= d);
            if (!any_range) flag = 0;                        // hist empty
            else {
                int mnb = bin_of(a), mxb = bin_of(bx);
                if (mnb != mxb) flag = any_valid ? 1 : 0;    // >= 2 bins
                else {
                    int mni = (int)c, mxi = (int)d;          // exact ints
                    flag = (any_valid && (mni != mnb || mxi != mnb)) ? 1 : 0;
                }
            }
            s_ns = flag ? -2.0f : 0.0f;
        }
        __syncthreads();
        ns = s_ns;
    }

    // ---- output ----
    float4 a0, a1, b0, b1, c0, c1, d0, d1;
    sm_pair(ns, va, a0, a1);
    sm_pair(ns, vb, b0, b1);
    sm_pair(ns, vc, c0, c1);
    sm_pair(ns, vd, d0, d1);

    __stcs(&o0[base],       a0);
    __stcs(&o0[base + 256], b0);
    __stcs(&o0[base + 512], c0);
    __stcs(&o0[base + 768], d0);
    __stcs(&o1[base],       a1);
    __stcs(&o1[base + 256], b1);
    __stcs(&o1[base + 512], c1);
    __stcs(&o1[base + 768], d1);
}

// ---------------------------------------------------------------------------
// Launch. d_in[0] = image_irr (16M fp32), d_in[1] = image_vis (dead in the
// reference — never read). d_out = msks[0] then msks[1], concatenated.
// ---------------------------------------------------------------------------
extern "C" void kernel_launch(void* const* d_in, const int* in_sizes, int n_in,
                              void* d_out, int out_size) {
    const float* irr = (const float*)d_in[0];
    float* out = (float*)d_out;

    wsm_kernel<<<N4 / 1024, 256>>>(irr, out);
}